// round 1
// baseline (speedup 1.0000x reference)
#include <cuda_runtime.h>
#include <math.h>

// Problem constants
#define B_TOTAL     2048
#define DIM         64
#define NODES_TOTAL 65535
#define SPLIT       8
#define NSUB        256      // 2^SPLIT subtrees
#define SUB_NODES   255      // internal nodes per subtree (8 levels)
#define BT          64       // batch tile per CTA

// Device scratch (static — no allocations allowed)
__device__ float g_kdiff[NODES_TOTAL * DIM];     // k0 - k1 per node
__device__ float g_probs8[NSUB * B_TOTAL];       // [depth8_leaf][batch]

// Shared memory layout (in floats)
#define QS_STRIDE 68
#define KD_STRIDE 260
#define SG_STRIDE 257
#define QS_OFF   0
#define KD_OFF   (QS_OFF + 64 * QS_STRIDE)             // 4352
#define SIG_OFF  (KD_OFF + 64 * KD_STRIDE)             // 20992
#define CUM_OFF  (SIG_OFF + 64 * SG_STRIDE)            // 37440
#define SMEM_FLOATS (CUM_OFF + 256 * 64)               // 53824
#define V_OFF    0   // V aliases Q+K region (dead after GEMM1); 16384 <= 20992
#define SMEM_BYTES (SMEM_FLOATS * 4)                   // 215,296 B

// ---------------------------------------------------------------------------
// K0: kdiff[n][k] = tree_key[n][0][k] - tree_key[n][1][k]
// ---------------------------------------------------------------------------
__global__ void kdiff_kernel(const float* __restrict__ tk) {
    int total = NODES_TOTAL * DIM;
    for (int i = blockIdx.x * blockDim.x + threadIdx.x; i < total;
         i += gridDim.x * blockDim.x) {
        int n = i >> 6, k = i & 63;
        g_kdiff[i] = tk[(n << 7) + k] - tk[(n << 7) + 64 + k];
    }
}

// ---------------------------------------------------------------------------
// Main kernel.  PHASE2=false: top 8 levels -> g_probs8.
//               PHASE2=true : one subtree x 64-batch tile -> atomicAdd(out).
//
// Leaf positions inside a (sub)tree use LSB-first path encoding ("pos"):
// expansion level e writes child0 in place at pos, child1 at pos + 2^e.
// Standard (reference) leaf index = bitrev8(pos); kdiff rows and V rows are
// loaded pre-permuted so all in-kernel indexing is pos-order.
// ---------------------------------------------------------------------------
template <bool PHASE2>
__global__ __launch_bounds__(256, 1)
void tree_kernel(const float* __restrict__ q,
                 const float* __restrict__ vtree,
                 float* __restrict__ out)
{
    extern __shared__ float sm[];
    const int tid    = threadIdx.x;
    const int s      = PHASE2 ? blockIdx.x : 0;                 // subtree id
    const int b_base = (PHASE2 ? blockIdx.y : blockIdx.x) * BT; // batch tile

    const int w = tid >> 5, l = tid & 31;

    // ---- Load Q transposed: Qs[k][b], warp-per-row, lane = 2 floats ----
    for (int b = w; b < BT; b += 8) {
        float2 v = *(const float2*)(q + (size_t)(b_base + b) * DIM + 2 * l);
        sm[QS_OFF + (2 * l)     * QS_STRIDE + b] = v.x;
        sm[QS_OFF + (2 * l + 1) * QS_STRIDE + b] = v.y;
    }

    // ---- Load kdiff transposed, rows in pos-order heap layout ----
    for (int r = w; r < SUB_NODES; r += 8) {
        int rp = r + 1;
        int e  = 31 - __clz(rp);          // level within (sub)tree, 0..7
        int posj = rp - (1 << e);         // LSB-first within-level position
        int j  = e ? (int)(__brev((unsigned)posj) >> (32 - e)) : 0; // std idx
        int lvl = e + (PHASE2 ? SPLIT : 0);
        long node = ((1L << lvl) - 1) + (long)s * (1 << e) + j;
        const float* src = g_kdiff + node * DIM;
        float2 v = *(const float2*)(src + 2 * l);
        sm[KD_OFF + (2 * l)     * KD_STRIDE + r] = v.x;
        sm[KD_OFF + (2 * l + 1) * KD_STRIDE + r] = v.y;
    }
    if (tid < 64) sm[KD_OFF + tid * KD_STRIDE + 255] = 0.f; // pad column
    __syncthreads();

    // ---- GEMM1: delta-logits [64 b x 256 n], sigmoid epilogue ----
    {
        const int tb = tid >> 5;          // 0..7  -> b0 = tb*8
        const int tn = tid & 31;          // n = tn + 32*m (strided: bank-free)
        const int b0 = tb * 8;
        float acc[8][8];
        #pragma unroll
        for (int i = 0; i < 8; i++)
            #pragma unroll
            for (int m = 0; m < 8; m++) acc[i][m] = 0.f;

        #pragma unroll 4
        for (int k = 0; k < 64; k++) {
            float a[8], bb[8];
            *(float4*)(a)     = *(const float4*)&sm[QS_OFF + k * QS_STRIDE + b0];
            *(float4*)(a + 4) = *(const float4*)&sm[QS_OFF + k * QS_STRIDE + b0 + 4];
            #pragma unroll
            for (int m = 0; m < 8; m++)
                bb[m] = sm[KD_OFF + k * KD_STRIDE + tn + 32 * m];
            #pragma unroll
            for (int i = 0; i < 8; i++)
                #pragma unroll
                for (int m = 0; m < 8; m++)
                    acc[i][m] = fmaf(a[i], bb[m], acc[i][m]);
        }
        // sigmoid + store sig[b][n] (stride 257 -> conflict-free both ways)
        #pragma unroll
        for (int m = 0; m < 8; m++) {
            int n = tn + 32 * m;
            if (n < SUB_NODES) {
                #pragma unroll
                for (int i = 0; i < 8; i++) {
                    float sg = 1.f / (1.f + __expf(-acc[i][m]));
                    sm[SIG_OFF + (b0 + i) * SG_STRIDE + n] = sg;
                }
            }
        }
    }
    __syncthreads();

    // ---- base prob into cum[0][b]; (phase2) load V into aliased region ----
    if (tid < BT) {
        sm[CUM_OFF + tid] = PHASE2 ? g_probs8[(size_t)s * B_TOTAL + b_base + tid]
                                   : 1.f;
    }
    if (PHASE2) {
        for (int r = w; r < 256; r += 8) {
            int leaf = (s << 8) + (int)(__brev((unsigned)r) >> 24);
            float2 v = *(const float2*)(vtree + (size_t)leaf * DIM + 2 * l);
            *(float2*)&sm[V_OFF + r * 64 + 2 * l] = v;
        }
    }
    __syncthreads();

    // ---- In-place hazard-free expansion over 8 levels ----
    #pragma unroll
    for (int e = 0; e < 8; e++) {
        int half  = 1 << e;
        int items = half * BT;
        for (int it = tid; it < items; it += 256) {
            int b = it & 63, pos = it >> 6;
            float sg = sm[SIG_OFF + b * SG_STRIDE + (half - 1 + pos)];
            float v  = sm[CUM_OFF + pos * 64 + b];
            sm[CUM_OFF + pos * 64 + b]          = v * sg;         // child 0
            sm[CUM_OFF + (pos + half) * 64 + b] = v * (1.f - sg); // child 1
        }
        __syncthreads();
    }

    if (!PHASE2) {
        // write depth-8 probs (convert pos -> standard leaf index)
        for (int it = tid; it < 256 * BT; it += 256) {
            int b = it & 63, pos = it >> 6;
            int leaf8 = (int)(__brev((unsigned)pos) >> 24);
            g_probs8[(size_t)leaf8 * B_TOTAL + b_base + b] =
                sm[CUM_OFF + pos * 64 + b];
        }
    } else {
        // ---- GEMM2: out[64 b x 64 d] += cum[64 x 256] @ V[256 x 64] ----
        const int kg = tid >> 7;          // K split: 2 groups of 128 leaves
        const int t  = tid & 127;
        const int b0 = (t >> 3) * 4;      // 16 b-tiles of 4
        const int d0 = (t & 7) * 8;       // 8  d-tiles of 8
        float acc[4][8];
        #pragma unroll
        for (int i = 0; i < 4; i++)
            #pragma unroll
            for (int j = 0; j < 8; j++) acc[i][j] = 0.f;

        const int l0 = kg * 128;
        #pragma unroll 2
        for (int ll = l0; ll < l0 + 128; ll++) {
            float a[4], vv[8];
            *(float4*)(a)      = *(const float4*)&sm[CUM_OFF + ll * 64 + b0];
            *(float4*)(vv)     = *(const float4*)&sm[V_OFF + ll * 64 + d0];
            *(float4*)(vv + 4) = *(const float4*)&sm[V_OFF + ll * 64 + d0 + 4];
            #pragma unroll
            for (int i = 0; i < 4; i++)
                #pragma unroll
                for (int j = 0; j < 8; j++)
                    acc[i][j] = fmaf(a[i], vv[j], acc[i][j]);
        }
        #pragma unroll
        for (int i = 0; i < 4; i++)
            #pragma unroll
            for (int j = 0; j < 8; j++)
                atomicAdd(&out[(size_t)(b_base + b0 + i) * DIM + d0 + j],
                          acc[i][j]);
    }
}

// ---------------------------------------------------------------------------
extern "C" void kernel_launch(void* const* d_in, const int* in_sizes, int n_in,
                              void* d_out, int out_size) {
    const float* q  = (const float*)d_in[0];   // (2048, 64)
    const float* tk = (const float*)d_in[1];   // (65535, 2, 64)
    const float* tv = (const float*)d_in[2];   // (65536, 64)
    float* out = (float*)d_out;                // (2048, 64)

    cudaFuncSetAttribute(tree_kernel<false>,
                         cudaFuncAttributeMaxDynamicSharedMemorySize, SMEM_BYTES);
    cudaFuncSetAttribute(tree_kernel<true>,
                         cudaFuncAttributeMaxDynamicSharedMemorySize, SMEM_BYTES);

    cudaMemsetAsync(out, 0, (size_t)B_TOTAL * DIM * sizeof(float));
    kdiff_kernel<<<4096, 1024>>>(tk);
    tree_kernel<false><<<B_TOTAL / BT, 256, SMEM_BYTES>>>(q, tv, out);
    tree_kernel<true><<<dim3(NSUB, B_TOTAL / BT), 256, SMEM_BYTES>>>(q, tv, out);
}